// round 16
// baseline (speedup 1.0000x reference)
#include <cuda_runtime.h>
#include <cuda_fp16.h>
#include <stdint.h>
#include <stddef.h>
#include <math.h>

#define SS   2048
#define DM   2048
#define NH   16
#define NKV  4
#define HD   128
#define NE   8
#define FF   4096
#define QKVN 3072
#define MAXROWS 5120
#define MAXTILES 40

// ---------------- scratch ----------------
__device__ float g_xln[SS*DM];
__device__ float g_qkv[SS*QKVN];
__device__ float g_V[NKV*SS*HD];
__device__ float g_P[67108864];
__device__ float g_res2[SS*DM];
__device__ float g_dout[MAXROWS*DM];
__device__ float g_topw[SS*2];
__device__ int   g_topid[SS*2];
__device__ int   g_cnt[NE];
__device__ int   g_cnt2[NE];
__device__ int   g_off[NE];
__device__ int   g_rows[MAXROWS];
__device__ float g_wv[MAXROWS];
__device__ int   g_slot[SS*2];
__device__ int   g_tileexp[MAXTILES];

// fp16 hi/lo scratch
__device__ __half g_x1h[SS*DM],  g_x1l[SS*DM];      // LN1 out
__device__ __half g_wqTh[QKVN*DM], g_wqTl[QKVN*DM]; // wqkv^T
__device__ __half g_woTh[DM*DM],   g_woTl[DM*DM];   // wo^T
__device__ __half g_Qh[NH*SS*HD],  g_Ql[NH*SS*HD];
__device__ __half g_Kh[NKV*SS*HD], g_Kl[NKV*SS*HD];
__device__ __half g_Ph[67108864],  g_Pl[67108864];
__device__ __half g_och[SS*DM],    g_ocl[SS*DM];    // attn out
// MoE fp16
__device__ __half g_xh[SS*DM];
__device__ __half g_gh[MAXROWS*FF];
__device__ __half g_wgh[NE*FF*DM];
__device__ __half g_wuh[NE*FF*DM];
__device__ __half g_wdh[NE*DM*FF];

// ================= fp16 helpers =================
__device__ __forceinline__ void cvt2(float x, float y, unsigned &h, unsigned &l) {
  __half hx = __float2half_rn(x), hy = __float2half_rn(y);
  __half lx = __float2half_rn(x - __half2float(hx));
  __half ly = __float2half_rn(y - __half2float(hy));
  h = (unsigned)__half_as_ushort(hx) | ((unsigned)__half_as_ushort(hy) << 16);
  l = (unsigned)__half_as_ushort(lx) | ((unsigned)__half_as_ushort(ly) << 16);
}
__device__ __forceinline__ unsigned cvt2h(float x, float y) {
  __half hx = __float2half_rn(x), hy = __float2half_rn(y);
  return (unsigned)__half_as_ushort(hx) | ((unsigned)__half_as_ushort(hy) << 16);
}

#define MMA_F16(ACC, A0,A1,A2,A3, B0,B1) \
  asm volatile("mma.sync.aligned.m16n8k16.row.col.f32.f16.f16.f32 " \
    "{%0,%1,%2,%3}, {%4,%5,%6,%7}, {%8,%9}, {%0,%1,%2,%3};" \
    : "+f"((ACC)[0]),"+f"((ACC)[1]),"+f"((ACC)[2]),"+f"((ACC)[3]) \
    : "r"(A0),"r"(A1),"r"(A2),"r"(A3),"r"(B0),"r"(B1))

// ============ split-3 fragment compute (shared by tiles) ============
__device__ __forceinline__ void comp_s3(float (&acc)[4][4][4],
    const unsigned* Ah, const unsigned* Al,
    const unsigned* Bh, const unsigned* Bl,
    int buf, int wm, int wn, int lane)
{
  unsigned ah[4][4], al[4][4], bh[4][2], bl[4][2];
#pragma unroll
  for (int i = 0; i < 4; i++)
#pragma unroll
    for (int e = 0; e < 4; e++) {
      int off = buf*1024 + (wm*4 + i)*128 + e*32 + lane;
      ah[i][e] = Ah[off];
      al[i][e] = Al[off];
    }
#pragma unroll
  for (int j = 0; j < 4; j++)
#pragma unroll
    for (int e = 0; e < 2; e++) {
      int off = buf*1024 + (wn*4 + j)*64 + e*32 + lane;
      bh[j][e] = Bh[off];
      bl[j][e] = Bl[off];
    }
#pragma unroll
  for (int i = 0; i < 4; i++)
#pragma unroll
    for (int j = 0; j < 4; j++) {
      MMA_F16(acc[i][j], al[i][0],al[i][1],al[i][2],al[i][3], bh[j][0],bh[j][1]);
      MMA_F16(acc[i][j], ah[i][0],ah[i][1],ah[i][2],ah[i][3], bl[j][0],bl[j][1]);
      MMA_F16(acc[i][j], ah[i][0],ah[i][1],ah[i][2],ah[i][3], bh[j][0],bh[j][1]);
    }
}

// ============ preconverted hi/lo tile: A [M][lda], B [N][ldb], both k-contig ============
__device__ __forceinline__ void f16_tile_pre(
    float (&acc)[4][4][4],
    const __half* __restrict__ Ahg, const __half* __restrict__ Alg, int lda, int m0,
    const __half* __restrict__ Bhg, const __half* __restrict__ Blg, int ldb, int n0,
    int kbeg, int kend,
    unsigned* __restrict__ Ah, unsigned* __restrict__ Al,
    unsigned* __restrict__ Bh, unsigned* __restrict__ Bl)
{
  const int tid = threadIdx.x, lane = tid & 31, warp = tid >> 5;
  const int wm = warp & 1, wn = warp >> 1;
  const int m = tid >> 1, kq = (tid & 1) * 8;
  const __half* aph = Ahg + (size_t)(m0 + m)*lda + kq;
  const __half* apl = Alg + (size_t)(m0 + m)*lda + kq;
  const __half* bph = Bhg + (size_t)(n0 + m)*ldb + kq;
  const __half* bpl = Blg + (size_t)(n0 + m)*ldb + kq;
  const int aidx = (m>>4)*128 + (((kq&8)>>2) | ((m&8)>>3))*32 + (m&7)*4;
  const int bidx = (m>>3)*64 + ((kq&8)>>3)*32 + (m&7)*4;

  uint4 avh, avl, bvh, bvl;
  auto load = [&](int k0) {
    avh = *(const uint4*)(aph + k0);
    avl = *(const uint4*)(apl + k0);
    bvh = *(const uint4*)(bph + k0);
    bvl = *(const uint4*)(bpl + k0);
  };
  auto store = [&](int buf) {
    *(uint4*)(Ah + buf*1024 + aidx) = avh;
    *(uint4*)(Al + buf*1024 + aidx) = avl;
    *(uint4*)(Bh + buf*1024 + bidx) = bvh;
    *(uint4*)(Bl + buf*1024 + bidx) = bvl;
  };

  load(kbeg);
  store(0);
  __syncthreads();
  int buf = 0;
  for (int k0 = kbeg + 16; k0 < kend; k0 += 16) {
    load(k0);
    comp_s3(acc, Ah, Al, Bh, Bl, buf, wm, wn, lane);
    store(buf ^ 1);
    __syncthreads();
    buf ^= 1;
  }
  comp_s3(acc, Ah, Al, Bh, Bl, buf, wm, wn, lane);
}

// ============ PV tile: A pre hi/lo, B fp32 [K][N=128] converted in-loader ============
__device__ __forceinline__ void f16_tile_pv(
    float (&acc)[4][4][4],
    const __half* __restrict__ Ahg, const __half* __restrict__ Alg, int lda, int m0,
    const float* __restrict__ B, int ldb,
    int kend,
    unsigned* __restrict__ Ah, unsigned* __restrict__ Al,
    unsigned* __restrict__ Bh, unsigned* __restrict__ Bl)
{
  const int tid = threadIdx.x, lane = tid & 31, warp = tid >> 5;
  const int wm = warp & 1, wn = warp >> 1;
  const int m = tid >> 1, kq = (tid & 1) * 8;
  const __half* aph = Ahg + (size_t)(m0 + m)*lda + kq;
  const __half* apl = Alg + (size_t)(m0 + m)*lda + kq;
  const int aidx = (m>>4)*128 + (((kq&8)>>2) | ((m&8)>>3))*32 + (m&7)*4;

  const float* bptr[2]; int bidx[2]; int bkq[2];
#pragma unroll
  for (int it = 0; it < 2; it++) {
    int q = tid + it*256;
    int n = q & 127, kq4 = (q >> 7) << 2;
    bkq[it] = kq4;
    bptr[it] = B + n;
    bidx[it] = (n>>3)*64 + ((kq4&8)>>3)*32 + (n&7)*4 + ((kq4&4)>>1);
  }

  uint4 avh, avl;
  float4 bv[2];
  auto load = [&](int k0) {
    avh = *(const uint4*)(aph + k0);
    avl = *(const uint4*)(apl + k0);
#pragma unroll
    for (int it = 0; it < 2; it++) {
      const float* p = bptr[it] + (size_t)(k0 + bkq[it]) * ldb;
      bv[it].x = p[0]; bv[it].y = p[ldb]; bv[it].z = p[2*ldb]; bv[it].w = p[3*ldb];
    }
  };
  auto store = [&](int buf) {
    *(uint4*)(Ah + buf*1024 + aidx) = avh;
    *(uint4*)(Al + buf*1024 + aidx) = avl;
#pragma unroll
    for (int it = 0; it < 2; it++) {
      unsigned h0,l0,h1,l1;
      cvt2(bv[it].x, bv[it].y, h0, l0);
      cvt2(bv[it].z, bv[it].w, h1, l1);
      *(uint2*)(Bh + buf*1024 + bidx[it]) = make_uint2(h0, h1);
      *(uint2*)(Bl + buf*1024 + bidx[it]) = make_uint2(l0, l1);
    }
  };

  load(0);
  store(0);
  __syncthreads();
  int buf = 0;
  for (int k0 = 16; k0 < kend; k0 += 16) {
    load(k0);
    comp_s3(acc, Ah, Al, Bh, Bl, buf, wm, wn, lane);
    store(buf ^ 1);
    __syncthreads();
    buf ^= 1;
  }
  comp_s3(acc, Ah, Al, Bh, Bl, buf, wm, wn, lane);
}

#define SMEM_F16S3 \
  __shared__ __align__(16) unsigned Ah[2*1024]; \
  __shared__ __align__(16) unsigned Al[2*1024]; \
  __shared__ __align__(16) unsigned Bh[2*1024]; \
  __shared__ __align__(16) unsigned Bl[2*1024];

#define EPI_SETUP() \
  const int lane = threadIdx.x & 31, warp = threadIdx.x >> 5; \
  const int wm = warp & 1, wn = warp >> 1; \
  const int g = lane >> 2, tg = lane & 3;

// ---------------- weight convert + transpose: W [K][N] -> Th/Tl [N][K] ----------------
__global__ __launch_bounds__(256) void k_cvtT(const float* __restrict__ W,
    __half* __restrict__ Th, __half* __restrict__ Tl, int K, int N)
{
  __shared__ float t[32][33];
  const int k0 = blockIdx.y*32, n0 = blockIdx.x*32;
  const int tx = threadIdx.x & 31, ty = threadIdx.x >> 5;
  for (int i = ty; i < 32; i += 8)
    t[i][tx] = W[(size_t)(k0+i)*N + n0+tx];
  __syncthreads();
  for (int i = ty; i < 32; i += 8) {
    const float v = t[tx][i];
    const __half h = __float2half_rn(v);
    const __half l = __float2half_rn(v - __half2float(h));
    Th[(size_t)(n0+i)*K + k0+tx] = h;
    Tl[(size_t)(n0+i)*K + k0+tx] = l;
  }
}

// convert all expert weights to fp16
__global__ __launch_bounds__(256) void k_cvtw(const float* __restrict__ wg,
    const float* __restrict__ wu, const float* __restrict__ wd)
{
  const size_t N = (size_t)NE*FF*DM;
  for (size_t i = ((size_t)blockIdx.x*256 + threadIdx.x)*4; i < N;
       i += (size_t)gridDim.x*1024) {
    float4 a = *(const float4*)(wg+i);
    *(uint2*)(g_wgh+i) = make_uint2(cvt2h(a.x,a.y), cvt2h(a.z,a.w));
    float4 b = *(const float4*)(wu+i);
    *(uint2*)(g_wuh+i) = make_uint2(cvt2h(b.x,b.y), cvt2h(b.z,b.w));
    float4 c = *(const float4*)(wd+i);
    *(uint2*)(g_wdh+i) = make_uint2(cvt2h(c.x,c.y), cvt2h(c.z,c.w));
  }
}

// ---------------- LayerNorm ----------------
__device__ __forceinline__ void ln_reduce(const float* __restrict__ x,
                                          float &mean, float &rstd)
{
  float s = 0.f, ss = 0.f;
  for (int d = threadIdx.x*4; d < DM; d += 1024) {
    float4 v = *(const float4*)(x + d);
    s  += v.x + v.y + v.z + v.w;
    ss += v.x*v.x + v.y*v.y + v.z*v.z + v.w*v.w;
  }
  __shared__ float shA[8], shB[8];
  const int lane = threadIdx.x & 31, wi = threadIdx.x >> 5;
  for (int o = 16; o; o >>= 1) { s += __shfl_xor_sync(0xffffffffu, s, o); ss += __shfl_xor_sync(0xffffffffu, ss, o); }
  if (lane == 0) { shA[wi] = s; shB[wi] = ss; }
  __syncthreads();
  float st = 0.f, sst = 0.f;
#pragma unroll
  for (int k = 0; k < 8; k++) { st += shA[k]; sst += shB[k]; }
  mean = st / (float)DM;
  const float var = sst / (float)DM - mean*mean;
  rstd = rsqrtf(var + 1e-5f);
}

// LN1: hidden -> hi/lo fp16 only
__global__ __launch_bounds__(256) void k_ln1(const float* __restrict__ hidden,
    const float* __restrict__ w, const float* __restrict__ b)
{
  const int row = blockIdx.x;
  const float* x = hidden + (size_t)row*DM;
  float mean, rstd;
  ln_reduce(x, mean, rstd);
  for (int d = threadIdx.x*4; d < DM; d += 1024) {
    float4 v = *(const float4*)(x + d);
    float4 wv = *(const float4*)(w + d);
    float4 bv = *(const float4*)(b + d);
    float o0 = (v.x-mean)*rstd*wv.x + bv.x;
    float o1 = (v.y-mean)*rstd*wv.y + bv.y;
    float o2 = (v.z-mean)*rstd*wv.z + bv.z;
    float o3 = (v.w-mean)*rstd*wv.w + bv.w;
    unsigned h0,l0,h1,l1;
    cvt2(o0,o1,h0,l0); cvt2(o2,o3,h1,l1);
    *(uint2*)(g_x1h + (size_t)row*DM + d) = make_uint2(h0,h1);
    *(uint2*)(g_x1l + (size_t)row*DM + d) = make_uint2(l0,l1);
  }
}

// LN2: res2 -> fp32 g_xln (router) + fp16 g_xh (MoE)
__global__ __launch_bounds__(256) void k_ln2(const float* __restrict__ w, const float* __restrict__ b)
{
  const int row = blockIdx.x;
  const float* x = g_res2 + (size_t)row*DM;
  float mean, rstd;
  ln_reduce(x, mean, rstd);
  for (int d = threadIdx.x*4; d < DM; d += 1024) {
    float4 v = *(const float4*)(x + d);
    float4 wv = *(const float4*)(w + d);
    float4 bv = *(const float4*)(b + d);
    float4 o;
    o.x = (v.x-mean)*rstd*wv.x + bv.x;
    o.y = (v.y-mean)*rstd*wv.y + bv.y;
    o.z = (v.z-mean)*rstd*wv.z + bv.z;
    o.w = (v.w-mean)*rstd*wv.w + bv.w;
    *(float4*)(g_xln + (size_t)row*DM + d) = o;
    *(uint2*)(g_xh + (size_t)row*DM + d) = make_uint2(cvt2h(o.x,o.y), cvt2h(o.z,o.w));
  }
}

// ---------------- QKV GEMM ----------------
__global__ __launch_bounds__(256) void t_gemm_qkv(const float* __restrict__ bias)
{
  SMEM_F16S3;
  float acc[4][4][4] = {};
  const int m0 = blockIdx.y * 128, n0 = blockIdx.x * 128;
  f16_tile_pre(acc, g_x1h, g_x1l, DM, m0, g_wqTh, g_wqTl, DM, n0, 0, DM, Ah, Al, Bh, Bl);
  EPI_SETUP();
#pragma unroll
  for (int i = 0; i < 4; i++)
#pragma unroll
    for (int j = 0; j < 4; j++) {
      const int row = m0 + wm*64 + i*16 + g;
      const int col = n0 + wn*32 + j*8 + tg*2;
      const float b0 = bias[col], b1 = bias[col+1];
      *(float2*)(g_qkv + (size_t)row*QKVN + col)     = make_float2(acc[i][j][0]+b0, acc[i][j][1]+b1);
      *(float2*)(g_qkv + (size_t)(row+8)*QKVN + col) = make_float2(acc[i][j][2]+b0, acc[i][j][3]+b1);
    }
}

// ---------------- RoPE + split -> hi/lo fp16 Q,K; fp32 V ----------------
__global__ __launch_bounds__(256) void k_rope(const float* __restrict__ cosb,
                                              const float* __restrict__ sinb)
{
  const int s = blockIdx.y;
  const int col = blockIdx.x * 256 + threadIdx.x;
  const float* qrow = g_qkv + (size_t)s * QKVN;
  const float x = qrow[col];
  if (col < NH*HD) {
    const int h = col >> 7, d = col & 127;
    const float c = cosb[s*HD+d], sn = sinb[s*HD+d];
    const float p = (d < 64) ? -qrow[col+64] : qrow[col-64];
    const float r = x*c + p*sn;
    const size_t idx = ((size_t)h*SS + s)*HD + d;
    const __half hh = __float2half_rn(r);
    g_Qh[idx] = hh;
    g_Ql[idx] = __float2half_rn(r - __half2float(hh));
  } else if (col < (NH+NKV)*HD) {
    const int cc = col - NH*HD;
    const int h = cc >> 7, d = cc & 127;
    const float c = cosb[s*HD+d], sn = sinb[s*HD+d];
    const float p = (d < 64) ? -qrow[col+64] : qrow[col-64];
    const float r = x*c + p*sn;
    const size_t idx = ((size_t)h*SS + s)*HD + d;
    const __half hh = __float2half_rn(r);
    g_Kh[idx] = hh;
    g_Kl[idx] = __float2half_rn(r - __half2float(hh));
  } else {
    const int cc = col - (NH+NKV)*HD;
    const int h = cc >> 7, d = cc & 127;
    g_V[((size_t)h*SS + s)*HD + d] = x;
  }
}

// ---------------- scores ----------------
__global__ __launch_bounds__(256) void t_scores(float scale)
{
  if (blockIdx.x > blockIdx.y) return;
  const int h = blockIdx.z;
  SMEM_F16S3;
  float acc[4][4][4] = {};
  const int m0 = blockIdx.y * 128, n0 = blockIdx.x * 128;
  f16_tile_pre(acc, g_Qh + (size_t)h*SS*HD, g_Ql + (size_t)h*SS*HD, HD, m0,
               g_Kh + (size_t)(h>>2)*SS*HD, g_Kl + (size_t)(h>>2)*SS*HD, HD, n0,
               0, HD, Ah, Al, Bh, Bl);
  EPI_SETUP();
  float* Ph = g_P + (size_t)h*SS*SS;
#pragma unroll
  for (int i = 0; i < 4; i++)
#pragma unroll
    for (int j = 0; j < 4; j++) {
      const int row = m0 + wm*64 + i*16 + g;
      const int col = n0 + wn*32 + j*8 + tg*2;
      *(float2*)(Ph + (size_t)row*SS + col)     = make_float2(acc[i][j][0]*scale, acc[i][j][1]*scale);
      *(float2*)(Ph + (size_t)(row+8)*SS + col) = make_float2(acc[i][j][2]*scale, acc[i][j][3]*scale);
    }
}

// ---------------- softmax -> hi/lo fp16 P ----------------
__global__ __launch_bounds__(256) void k_softmax()
{
  const int i = blockIdx.x, h = blockIdx.y;
  const size_t base = ((size_t)h*SS + i)*SS;
  const float* row = g_P + base;
  const int jm = i;
  const int jend = ((i >> 7) + 1) << 7;
  __shared__ float buf[2048];
  __shared__ float redA[8], redB[8];
  const int tid = threadIdx.x;
  float mx = -1e30f;
  for (int j = tid; j <= jm; j += 256) { float v = row[j]; buf[j] = v; mx = fmaxf(mx, v); }
  for (int o = 16; o; o >>= 1) mx = fmaxf(mx, __shfl_xor_sync(0xffffffffu, mx, o));
  if ((tid & 31) == 0) redA[tid >> 5] = mx;
  __syncthreads();
  float m = redA[0];
#pragma unroll
  for (int k = 1; k < 8; k++) m = fmaxf(m, redA[k]);
  float s = 0.f;
  for (int j = tid; j <= jm; j += 256) { float e = expf(buf[j] - m); buf[j] = e; s += e; }
  for (int o = 16; o; o >>= 1) s += __shfl_xor_sync(0xffffffffu, s, o);
  if ((tid & 31) == 0) redB[tid >> 5] = s;
  __syncthreads();
  float st = 0.f;
#pragma unroll
  for (int k = 0; k < 8; k++) st += redB[k];
  const float inv = 1.f / st;
  for (int j = tid; j < jend; j += 256) {
    const float v = (j <= jm) ? buf[j]*inv : 0.f;
    const __half hh = __float2half_rn(v);
    g_Ph[base + j] = hh;
    g_Pl[base + j] = __float2half_rn(v - __half2float(hh));
  }
}

// ---------------- PV -> hi/lo fp16 oc ----------------
__global__ __launch_bounds__(256) void t_pv()
{
  const int h = blockIdx.z, bm = blockIdx.y;
  SMEM_F16S3;
  float acc[4][4][4] = {};
  const int m0 = bm * 128;
  const int kend = (bm + 1) * 128;
  f16_tile_pv(acc, g_Ph + (size_t)h*SS*SS, g_Pl + (size_t)h*SS*SS, SS, m0,
              g_V + (size_t)(h>>2)*SS*HD, HD, kend, Ah, Al, Bh, Bl);
  EPI_SETUP();
#pragma unroll
  for (int i = 0; i < 4; i++)
#pragma unroll
    for (int j = 0; j < 4; j++) {
      const int row = m0 + wm*64 + i*16 + g;
      const int col = h*HD + wn*32 + j*8 + tg*2;
      unsigned h0,l0,h1,l1;
      cvt2(acc[i][j][0], acc[i][j][1], h0, l0);
      cvt2(acc[i][j][2], acc[i][j][3], h1, l1);
      *(unsigned*)(g_och + (size_t)row*DM + col)     = h0;
      *(unsigned*)(g_ocl + (size_t)row*DM + col)     = l0;
      *(unsigned*)(g_och + (size_t)(row+8)*DM + col) = h1;
      *(unsigned*)(g_ocl + (size_t)(row+8)*DM + col) = l1;
    }
}

// ---------------- O proj + residual ----------------
__global__ __launch_bounds__(256) void t_oproj(const float* __restrict__ bias,
                                               const float* __restrict__ resid)
{
  SMEM_F16S3;
  float acc[4][4][4] = {};
  const int m0 = blockIdx.y * 128, n0 = blockIdx.x * 128;
  f16_tile_pre(acc, g_och, g_ocl, DM, m0, g_woTh, g_woTl, DM, n0, 0, DM, Ah, Al, Bh, Bl);
  EPI_SETUP();
#pragma unroll
  for (int i = 0; i < 4; i++)
#pragma unroll
    for (int j = 0; j < 4; j++) {
      const int row = m0 + wm*64 + i*16 + g;
      const int col = n0 + wn*32 + j*8 + tg*2;
      const float b0 = bias[col], b1 = bias[col+1];
      float2 r0 = *(const float2*)(resid + (size_t)row*DM + col);
      float2 r1 = *(const float2*)(resid + (size_t)(row+8)*DM + col);
      *(float2*)(g_res2 + (size_t)row*DM + col)     = make_float2(acc[i][j][0]+b0+r0.x, acc[i][j][1]+b1+r0.y);
      *(float2*)(g_res2 + (size_t)(row+8)*DM + col) = make_float2(acc[i][j][2]+b0+r1.x, acc[i][j][3]+b1+r1.y);
    }
}

__global__ __launch_bounds__(256) void k_copyres(float* __restrict__ dst)
{
  const int i = blockIdx.x * 256 + threadIdx.x;
  ((float4*)dst)[i] = ((const float4*)g_res2)[i];
}

// ---------------- router + sparsemixer ----------------
__global__ void k_zero() { if (threadIdx.x < NE) g_cnt[threadIdx.x] = 0; }

__global__ __launch_bounds__(256) void k_router(const float* __restrict__ gw)
{
  const int t = blockIdx.x;
  const float* x = g_xln + (size_t)t * DM;
  float acc[NE];
#pragma unroll
  for (int e = 0; e < NE; e++) acc[e] = 0.f;
  for (int d = threadIdx.x; d < DM; d += 256) {
    const float xv = x[d];
    const float* gr = gw + d * NE;
#pragma unroll
    for (int e = 0; e < NE; e++) acc[e] += xv * gr[e];
  }
  __shared__ float sh[NE][8];
  const int lane = threadIdx.x & 31, w = threadIdx.x >> 5;
#pragma unroll
  for (int e = 0; e < NE; e++) {
    float v = acc[e];
    for (int o = 16; o; o >>= 1) v += __shfl_xor_sync(0xffffffffu, v, o);
    if (lane == 0) sh[e][w] = v;
  }
  __syncthreads();
  if (threadIdx.x == 0) {
    float s[NE];
#pragma unroll
    for (int e = 0; e < NE; e++) {
      float v = 0.f;
#pragma unroll
      for (int k = 0; k < 8; k++) v += sh[e][k];
      s[e] = v;
    }
    const float teps = 0.02f;
    int i1 = 0;
    for (int e = 1; e < NE; e++) if (s[e] > s[i1]) i1 = e;
    const float mx1 = s[i1];
    float den = 0.f;
    for (int e = 0; e < NE; e++) {
      const float f = fmaxf(fabsf(s[e]), mx1);
      if (!((mx1 - s[e]) / f > teps)) den += expf(s[e] - mx1);
    }
    const float w1 = 1.f / den;
    int i2 = -1; float mx2 = -INFINITY;
    for (int e = 0; e < NE; e++) if (e != i1 && s[e] > mx2) { mx2 = s[e]; i2 = e; }
    float den2 = 0.f;
    for (int e = 0; e < NE; e++) {
      if (e == i1) continue;
      const float f = fmaxf(fabsf(s[e]), mx2);
      if (!((mx2 - s[e]) / f > teps)) den2 += expf(s[e] - mx2);
    }
    const float w2 = 1.f / den2;
    g_topw[t*2] = w1; g_topw[t*2+1] = w2;
    g_topid[t*2] = i1; g_topid[t*2+1] = i2;
    atomicAdd(&g_cnt[i1], 1); atomicAdd(&g_cnt[i2], 1);
  }
}

__global__ __launch_bounds__(256) void k_setup()
{
  const int tid = threadIdx.x;
  if (tid == 0) {
    for (int t = 0; t < MAXTILES; t++) g_tileexp[t] = -1;
    int o = 0;
    for (int e = 0; e < NE; e++) {
      g_off[e] = o;
      const int tiles = (g_cnt[e] + 127) >> 7;
      for (int t = 0; t < tiles; t++) g_tileexp[(o >> 7) + t] = e;
      o += tiles << 7;
    }
  }
  for (int i = tid; i < MAXROWS; i += 256) { g_rows[i] = 0; g_wv[i] = 0.f; }
  if (tid < NE) g_cnt2[tid] = 0;
}

__global__ __launch_bounds__(256) void k_scatter()
{
  const int t = blockIdx.x * 256 + threadIdx.x;
  if (t >= SS) return;
#pragma unroll
  for (int j = 0; j < 2; j++) {
    const int e = g_topid[t*2+j];
    const int pos = g_off[e] + atomicAdd(&g_cnt2[e], 1);
    g_rows[pos] = t;
    g_wv[pos] = g_topw[t*2+j];
    g_slot[t*2+j] = pos;
  }
}

// ================= MoE fp16 direct-load tiles, BK=16 =================
__global__ __launch_bounds__(256) void h_moe_gu()
{
  const int e = g_tileexp[blockIdx.y];
  if (e < 0) return;
  __shared__ __align__(16) unsigned Ah[2*1024];
  __shared__ __align__(16) unsigned Bg[2*1024];
  __shared__ __align__(16) unsigned Bu[2*1024];
  float ag[4][4][4] = {}, au[4][4][4] = {};
  const int m0 = blockIdx.y * 128, n0 = blockIdx.x * 128;
  const int tid = threadIdx.x, lane = tid & 31, warp = tid >> 5;
  const int wm = warp & 1, wn = warp >> 1;

  const int m = tid >> 1, kq = (tid & 1) * 8;
  const int tok = g_rows[m0 + m];
  const __half* ap = g_xh + (size_t)tok*DM + kq;
  const size_t br = (size_t)e*FF + n0 + m;
  const __half* gp = g_wgh + br*DM + kq;
  const __half* up = g_wuh + br*DM + kq;
  const int asto = (m>>4)*128 + (((kq&8)>>2) | ((m&8)>>3))*32 + (m&7)*4;
  const int bsto = (m>>3)*64 + ((kq&8)>>3)*32 + (m&7)*4;

  uint4 av, gv, uv;
  auto load = [&](int k0) {
    av = *(const uint4*)(ap + k0);
    gv = *(const uint4*)(gp + k0);
    uv = *(const uint4*)(up + k0);
  };
  auto store = [&](int buf) {
    *(uint4*)(Ah + buf*1024 + asto) = av;
    *(uint4*)(Bg + buf*1024 + bsto) = gv;
    *(uint4*)(Bu + buf*1024 + bsto) = uv;
  };
  auto comp = [&](int buf) {
    unsigned ah[4][4], bg[4][2], bu[4][2];
#pragma unroll
    for (int i = 0; i < 4; i++)
#pragma unroll
      for (int ee = 0; ee < 4; ee++)
        ah[i][ee] = Ah[buf*1024 + (wm*4 + i)*128 + ee*32 + lane];
#pragma unroll
    for (int j = 0; j < 4; j++)
#pragma unroll
      for (int ee = 0; ee < 2; ee++) {
        int off = buf*1024 + (wn*4 + j)*64 + ee*32 + lane;
        bg[j][ee] = Bg[off];
        bu[j][ee] = Bu[off];
      }
#pragma unroll
    for (int i = 0; i < 4; i++)
#pragma unroll
      for (int j = 0; j < 4; j++) {
        MMA_F16(ag[i][j], ah[i][0],ah[i][1],ah[i][2],ah[i][3], bg[j][0],bg[j][1]);
        MMA_F16(au[i][j], ah[i][0],ah[i][1],ah[i][2],ah[i][3], bu[j][0],bu[j][1]);
      }
  };

  load(0);
  store(0);
  __syncthreads();
  int buf = 0;
  for (int k0 = 16; k0 < DM; k0 += 16) {
    load(k0);
    comp(buf);
    store(buf ^ 1);
    __syncthreads();
    buf ^= 1;
  }
  comp(buf);

  const int g = lane >> 2, tg = lane & 3;
#pragma unroll
  for (int i = 0; i < 4; i++)
#pragma unroll
    for (int j = 0; j < 4; j++) {
      const int row = m0 + wm*64 + i*16 + g;
      const int col = n0 + wn*32 + j*8 + tg*2;
      const float g0 = ag[i][j][0], g1 = ag[i][j][1];
      const float g2 = ag[i][j][2], g3 = ag[i][j][3];
      const float h0 = g0/(1.f+expf(-g0)) * au[i][j][0];
      const float h1 = g1/(1.f+expf(-g1)) * au[i][j][1];
      const float h2 = g2/(1.f+expf(-g2)) * au[i][j][2];
      const float h3 = g3/(1.f+expf(-g3)) * au[i][j][3];
      *(unsigned*)(g_gh + (size_t)row*FF + col)     = cvt2h(h0, h1);
      *(unsigned*)(g_gh + (size_t)(row+8)*FF + col) = cvt2h(h2, h3);
    }
}

__global__ __launch_bounds__(256) void h_moe_down()
{
  const int e = g_tileexp[blockIdx.y];
  if (e < 0) return;
  __shared__ __align__(16) unsigned Ah[2*1024];
  __shared__ __align__(16) unsigned Bh[2*1024];
  float acc[4][4][4] = {};
  const int m0 = blockIdx.y * 128, n0 = blockIdx.x * 128;
  const int tid = threadIdx.x, lane = tid & 31, warp = tid >> 5;
  const int wm = warp & 1, wn = warp >> 1;

  const int m = tid >> 1, kq = (tid & 1) * 8;
  const __half* ap = g_gh + (size_t)(m0 + m)*FF + kq;
  const __half* bp = g_wdh + ((size_t)e*DM + n0 + m)*FF + kq;
  const int asto = (m>>4)*128 + (((kq&8)>>2) | ((m&8)>>3))*32 + (m&7)*4;
  const int bsto = (m>>3)*64 + ((kq&8)>>3)*32 + (m&7)*4;

  uint4 av, bv;
  auto load = [&](int k0) {
    av = *(const uint4*)(ap + k0);
    bv = *(const uint4*)(bp + k0);
  };
  auto store = [&](int buf) {
    *(uint4*)(Ah + buf*1024 + asto) = av;
    *(uint4*)(Bh + buf*1024 + bsto) = bv;
  };
  auto comp = [&](int buf) {
    unsigned ah[4][4], bh[4][2];
#pragma unroll
    for (int i = 0; i < 4; i++)
#pragma unroll
      for (int ee = 0; ee < 4; ee++)
        ah[i][ee] = Ah[buf*1024 + (wm*4 + i)*128 + ee*32 + lane];
#pragma unroll
    for (int j = 0; j < 4; j++)
#pragma unroll
      for (int ee = 0; ee < 2; ee++)
        bh[j][ee] = Bh[buf*1024 + (wn*4 + j)*64 + ee*32 + lane];
#pragma unroll
    for (int i = 0; i < 4; i++)
#pragma unroll
      for (int j = 0; j < 4; j++)
        MMA_F16(acc[i][j], ah[i][0],ah[i][1],ah[i][2],ah[i][3], bh[j][0],bh[j][1]);
  };

  load(0);
  store(0);
  __syncthreads();
  int buf = 0;
  for (int k0 = 16; k0 < FF; k0 += 16) {
    load(k0);
    comp(buf);
    store(buf ^ 1);
    __syncthreads();
    buf ^= 1;
  }
  comp(buf);

  const int g = lane >> 2, tg = lane & 3;
#pragma unroll
  for (int i = 0; i < 4; i++)
#pragma unroll
    for (int j = 0; j < 4; j++) {
      const int row = m0 + wm*64 + i*16 + g;
      const int col = n0 + wn*32 + j*8 + tg*2;
      const float w0 = g_wv[row], w1 = g_wv[row+8];
      *(float2*)(g_dout + (size_t)row*DM + col)     = make_float2(acc[i][j][0]*w0, acc[i][j][1]*w0);
      *(float2*)(g_dout + (size_t)(row+8)*DM + col) = make_float2(acc[i][j][2]*w1, acc[i][j][3]*w1);
    }
}

__global__ __launch_bounds__(256) void k_combine(float* __restrict__ out)
{
  const int t = blockIdx.y;
  const int d = blockIdx.x * 256 + threadIdx.x;
  const int s0 = g_slot[t*2], s1 = g_slot[t*2+1];
  out[(size_t)t*DM + d] = g_dout[(size_t)s0*DM + d] + g_dout[(size_t)s1*DM + d];
}

// ---------------- launch ----------------
extern "C" void kernel_launch(void* const* d_in, const int* in_sizes, int n_in,
                              void* d_out, int out_size)
{
  const float* hidden = (const float*)d_in[0];
  const float* cosb   = (const float*)d_in[1];
  const float* sinb   = (const float*)d_in[2];
  const float* ln1w   = (const float*)d_in[3];
  const float* ln1b   = (const float*)d_in[4];
  const float* ln2w   = (const float*)d_in[5];
  const float* ln2b   = (const float*)d_in[6];
  const float* wqkv   = (const float*)d_in[7];
  const float* bqkv   = (const float*)d_in[8];
  const float* wo     = (const float*)d_in[9];
  const float* bo     = (const float*)d_in[10];
  const float* gatew  = (const float*)d_in[11];
  const float* wgate  = (const float*)d_in[12];
  const float* wup    = (const float*)d_in[13];
  const float* wdown  = (const float*)d_in[14];
  float* out = (float*)d_out;

  __half *wqTh, *wqTl, *woTh, *woTl;
  cudaGetSymbolAddress((void**)&wqTh, g_wqTh);
  cudaGetSymbolAddress((void**)&wqTl, g_wqTl);
  cudaGetSymbolAddress((void**)&woTh, g_woTh);
  cudaGetSymbolAddress((void**)&woTl, g_woTl);

  k_zero<<<1, 32>>>();
  k_cvtw<<<16384, 256>>>(wgate, wup, wdown);
  k_cvtT<<<dim3(QKVN/32, DM/32), 256>>>(wqkv, wqTh, wqTl, DM, QKVN);
  k_cvtT<<<dim3(DM/32, DM/32), 256>>>(wo, woTh, woTl, DM, DM);
  k_ln1<<<SS, 256>>>(hidden, ln1w, ln1b);
  t_gemm_qkv<<<dim3(QKVN/128, SS/128), 256>>>(bqkv);
  k_rope<<<dim3(QKVN/256, SS), 256>>>(cosb, sinb);
  t_scores<<<dim3(SS/128, SS/128, NH), 256>>>(0.08838834764831845f);
  k_softmax<<<dim3(SS, NH), 256>>>();
  t_pv<<<dim3(1, SS/128, NH), 256>>>();
  t_oproj<<<dim3(DM/128, SS/128), 256>>>(bo, hidden);
  if (out_size >= 2 * SS * DM)
    k_copyres<<<(SS*DM/4)/256, 256>>>(out + (size_t)SS*DM);
  k_ln2<<<SS, 256>>>(ln2w, ln2b);
  k_router<<<SS, 256>>>(gatew);
  k_setup<<<1, 256>>>();
  k_scatter<<<(SS + 255)/256, 256>>>();
  h_moe_gu<<<dim3(FF/128, MAXTILES), 256>>>();
  h_moe_down<<<dim3(DM/128, MAXTILES), 256>>>();
  k_combine<<<dim3(DM/256, SS), 256>>>(out);
}